// round 2
// baseline (speedup 1.0000x reference)
#include <cuda_runtime.h>
#include <cuda_bf16.h>

// SemiLoss focal loss:
//   logits  : [N, K, P] f32   (N=B*S, P=H*W)
//   seg     : [N, P]    int64 or int32 (runtime-detected)
//   label   : [N]       int64 or int32 (same dtype as seg)
//   loss = sum_{n: label[n]!=0} sum_p -(1-exp(lp))^6 * lp   / count(label!=0)
//   out = [loss, 0, loss] (f32)

#define GAMMA_POW6 1  // gamma = 6 fixed

// ---- device globals (no allocs allowed) ----
__device__ double        g_total;       // sum of (1-pt)^6 * lp over masked pixels
__device__ int           g_cnt;         // count of nonzero labels
__device__ int           g_is64;        // 1 if seg/label are int64
__device__ unsigned char g_mask[8192];  // per-row active flag

// ---------------------------------------------------------------------------
// Init: reset accumulators, sniff dtype, build row mask + count.
// Single block.
// ---------------------------------------------------------------------------
__global__ void semiloss_init(const void* __restrict__ seg,
                              const void* __restrict__ label,
                              int N)
{
    __shared__ int s_is64;
    int t = threadIdx.x;

    if (t < 32) {
        // If int64 (LE) with values in [0,11), every odd 32-bit word is 0.
        // If int32, odd words are random classes in [0,11): P(all 32 == 0) ~ 11^-32.
        const int* w = (const int*)seg;
        int v = w[2 * t + 1];
        unsigned b = __ballot_sync(0xffffffffu, v == 0);
        if (t == 0) s_is64 = (b == 0xffffffffu) ? 1 : 0;
    }
    __syncthreads();

    if (t == 0) {
        g_is64  = s_is64;
        g_total = 0.0;
        g_cnt   = 0;
    }
    __syncthreads();

    int local = 0;
    for (int n = t; n < N; n += blockDim.x) {
        long long lv;
        if (s_is64) lv = ((const long long*)label)[n];
        else        lv = (long long)((const int*)label)[n];
        unsigned char m = (lv != 0) ? 1 : 0;
        g_mask[n] = m;
        local += m;
    }
    // block reduce count
    __shared__ int s_cnt[32];
    // warp reduce
    for (int off = 16; off > 0; off >>= 1)
        local += __shfl_down_sync(0xffffffffu, local, off);
    if ((t & 31) == 0) s_cnt[t >> 5] = local;
    __syncthreads();
    if (t < 32) {
        int nw = (blockDim.x + 31) >> 5;
        int v = (t < nw) ? s_cnt[t] : 0;
        for (int off = 16; off > 0; off >>= 1)
            v += __shfl_down_sync(0xffffffffu, v, off);
        if (t == 0) atomicAdd(&g_cnt, v);
    }
}

// ---------------------------------------------------------------------------
// Main gather-reduce. grid = (blocksPerRow, N), block = 256 threads,
// 4 pixels per thread.
// ---------------------------------------------------------------------------
__device__ __forceinline__ float focal_term(float lp)
{
    float pt = expf(lp);
    float u  = 1.0f - pt;
    float u2 = u * u;
    return u2 * u2 * u2 * lp;   // NOTE: positive form; negated at the end
}

__global__ __launch_bounds__(256)
void semiloss_main(const float* __restrict__ logits,
                   const void*  __restrict__ seg,
                   int K, int P)
{
    int n = blockIdx.y;
    if (!g_mask[n]) return;

    const float* base = logits + (size_t)n * (size_t)K * (size_t)P;
    int p0 = (blockIdx.x * blockDim.x + threadIdx.x) * 4;

    double acc = 0.0;
    int is64 = g_is64;

    if (p0 + 4 <= P) {
        int c0, c1, c2, c3;
        if (is64) {
            const longlong2* s =
                (const longlong2*)((const char*)seg + ((size_t)n * P + p0) * 8);
            longlong2 a = s[0];
            longlong2 b = s[1];
            c0 = (int)a.x; c1 = (int)a.y; c2 = (int)b.x; c3 = (int)b.y;
        } else {
            const int4* s =
                (const int4*)((const char*)seg + ((size_t)n * P + p0) * 4);
            int4 a = *s;
            c0 = a.x; c1 = a.y; c2 = a.z; c3 = a.w;
        }
        float l0 = __ldg(base + (size_t)c0 * P + p0 + 0);
        float l1 = __ldg(base + (size_t)c1 * P + p0 + 1);
        float l2 = __ldg(base + (size_t)c2 * P + p0 + 2);
        float l3 = __ldg(base + (size_t)c3 * P + p0 + 3);
        acc += (double)focal_term(l0);
        acc += (double)focal_term(l1);
        acc += (double)focal_term(l2);
        acc += (double)focal_term(l3);
    } else {
        for (int p = p0; p < P; ++p) {
            int c;
            if (is64) c = (int)((const long long*)seg)[(size_t)n * P + p];
            else      c = ((const int*)seg)[(size_t)n * P + p];
            acc += (double)focal_term(__ldg(base + (size_t)c * P + p));
        }
    }

    // block reduction (double)
    for (int off = 16; off > 0; off >>= 1)
        acc += __shfl_down_sync(0xffffffffu, acc, off);
    __shared__ double s_part[8];
    int lane = threadIdx.x & 31, wid = threadIdx.x >> 5;
    if (lane == 0) s_part[wid] = acc;
    __syncthreads();
    if (wid == 0) {
        double v = (lane < (blockDim.x >> 5)) ? s_part[lane] : 0.0;
        for (int off = 4; off > 0; off >>= 1)
            v += __shfl_down_sync(0xffffffffu, v, off);
        if (lane == 0) atomicAdd(&g_total, v);
    }
}

// ---------------------------------------------------------------------------
// Finish: loss = -total / cnt; out = [loss, 0, loss, 0, 0, ...]
// ---------------------------------------------------------------------------
__global__ void semiloss_finish(float* __restrict__ out, int out_size)
{
    int i = blockIdx.x * blockDim.x + threadIdx.x;
    if (i >= out_size) return;
    float v = 0.0f;
    if (i == 0 || i == 2) {
        double c = (double)g_cnt;
        v = (float)(-g_total / c);
    }
    out[i] = v;
}

// ---------------------------------------------------------------------------
extern "C" void kernel_launch(void* const* d_in, const int* in_sizes, int n_in,
                              void* d_out, int out_size)
{
    const float* logits = (const float*)d_in[0];
    const void*  seg    = d_in[1];
    const void*  label  = d_in[2];

    int N = in_sizes[2];                 // B*S
    int P = in_sizes[1] / N;             // H*W
    int K = in_sizes[0] / in_sizes[1];   // classes

    semiloss_init<<<1, 128>>>(seg, label, N);

    const int THREADS = 256;
    const int PX_PER_BLOCK = THREADS * 4;
    int blocksPerRow = (P + PX_PER_BLOCK - 1) / PX_PER_BLOCK;
    dim3 grid(blocksPerRow, N);
    semiloss_main<<<grid, THREADS>>>(logits, seg, K, P);

    int fb = (out_size + 255) / 256;
    semiloss_finish<<<fb, 256>>>((float*)d_out, out_size);
}